// round 10
// baseline (speedup 1.0000x reference)
#include <cuda_runtime.h>
#include <math.h>
#include <stdint.h>

#define NB        8192
#define CELLS     49
#define CH        30
#define ROW       (CELLS*CH)      // 1470 floats per image
#define NIMG      4               // images per CTA
#define QUAD_ROW  (NIMG*ROW)      // 5880 floats
#define QUAD_BYTES (QUAD_ROW*4)   // 23520 bytes (16B multiple)
#define MAXBOX    98
#define NPART     (NB/NIMG)       // 2048 partials
#define NMID      16

// Stage-1 partials: one float4 {noobj, cls, coord, obj} per image-quad.
__device__ float4  g_part4[NPART];
// Stage-2 partials.
__device__ double4 g_mid[NMID];

__device__ __forceinline__ uint32_t smem_u32(const void* p) {
    uint32_t a;
    asm("{ .reg .u64 t; cvta.to.shared.u64 t, %1; cvt.u32.u64 %0, t; }"
        : "=r"(a) : "l"(p));
    return a;
}

__device__ __forceinline__ void mbar_wait(uint32_t mbar, uint32_t parity) {
    asm volatile(
        "{\n\t"
        ".reg .pred P1;\n\t"
        "WAIT_LOOP_%=:\n\t"
        "mbarrier.try_wait.parity.acquire.cta.shared::cta.b64 P1, [%0], %1, 0x989680;\n\t"
        "@P1 bra.uni WAIT_DONE_%=;\n\t"
        "bra.uni WAIT_LOOP_%=;\n\t"
        "WAIT_DONE_%=:\n\t"
        "}"
        :: "r"(mbar), "r"(parity) : "memory");
}

__global__ void __launch_bounds__(512)
yolo_k1(const float* __restrict__ pred, const float* __restrict__ targ)
{
    __shared__ float  sp[QUAD_ROW];
    __shared__ float  st[QUAD_ROW];
    __shared__ float4 s_pbox[NIMG][MAXBOX];
    __shared__ float  s_red[4][16];
    __shared__ __align__(8) unsigned long long s_mbar;

    const int tid = threadIdx.x;
    const uint32_t mbar = smem_u32(&s_mbar);
    const uint32_t sp_a = smem_u32(sp);
    const uint32_t st_a = smem_u32(st);

    // ---- bulk-async (TMA path) load of all four image-rows ----
    if (tid == 0) {
        asm volatile("mbarrier.init.shared.b64 [%0], 1;" :: "r"(mbar) : "memory");
        asm volatile("fence.proxy.async.shared::cta;" ::: "memory");
    }
    __syncthreads();
    if (tid == 0) {
        asm volatile("mbarrier.arrive.expect_tx.shared.b64 _, [%0], %1;"
                     :: "r"(mbar), "r"(2u * QUAD_BYTES) : "memory");
        const float* psrc = pred + (size_t)blockIdx.x * QUAD_ROW;
        const float* tsrc = targ + (size_t)blockIdx.x * QUAD_ROW;
        asm volatile(
            "cp.async.bulk.shared::cta.global.mbarrier::complete_tx::bytes [%0], [%1], %2, [%3];"
            :: "r"(sp_a), "l"(psrc), "r"((uint32_t)QUAD_BYTES), "r"(mbar) : "memory");
        asm volatile(
            "cp.async.bulk.shared::cta.global.mbarrier::complete_tx::bytes [%0], [%1], %2, [%3];"
            :: "r"(st_a), "l"(tsrc), "r"((uint32_t)QUAD_BYTES), "r"(mbar) : "memory");
    }
    mbar_wait(mbar, 0);

    const int sub  = tid >> 7;        // 0..3: which image
    const int lt   = tid & 127;
    const int base = sub * ROW;

    float a_noobj = 0.0f, a_cls = 0.0f, a_coord = 0.0f, a_obj = 0.0f;

    // ---- pred boxes -> smem (empty box if cell unmasked) ----
    bool mymask = false;
    int  myoff  = 0;
    if (lt < MAXBOX) {
        const int c = lt >> 1;
        myoff  = base + c * CH + (lt & 1) * 5;
        mymask = st[base + c * CH + 4] > 0.0f;
        float4 box;
        if (mymask) {
            const float cx = sp[myoff + 0], cy = sp[myoff + 1];
            const float w  = sp[myoff + 2], h  = sp[myoff + 3];
            box = make_float4(cx - 0.5f * w, cy - 0.5f * h,
                              cx + 0.5f * w, cy + 0.5f * h);
        } else {
            box = make_float4(1e30f, 1e30f, -1e30f, -1e30f);
        }
        s_pbox[sub][lt] = box;
    }

    // ---- per-cell losses (before barrier; independent of s_pbox) ----
    if (lt < CELLS) {
        const float* pc = sp + base + lt * CH;
        const float* tc = st + base + lt * CH;
        if (tc[4] == 0.0f) {
            const float d4 = pc[4];
            const float d9 = pc[9] - tc[9];
            a_noobj = d4 * d4 + d9 * d9;
        } else {
            const float2* pc2 = reinterpret_cast<const float2*>(pc + 10);
            const float2* tc2 = reinterpret_cast<const float2*>(tc + 10);
            float s = 0.0f;
            #pragma unroll
            for (int k = 0; k < 10; k++) {
                const float2 a = pc2[k], bb = tc2[k];
                const float d0 = a.x - bb.x;
                const float d1 = a.y - bb.y;
                s += d0 * d0 + d1 * d1;
            }
            a_cls = s;
        }
    }
    __syncthreads();

    // ---- cmask + coord/obj losses (thread j owns target box j) ----
    if (lt < MAXBOX && mymask) {
        const float tcx = st[myoff + 0], tcy = st[myoff + 1];
        const float tw  = st[myoff + 2], th  = st[myoff + 3];
        const float tx0 = tcx - 0.5f * tw, ty0 = tcy - 0.5f * th;
        const float tx1 = tcx + 0.5f * tw, ty1 = tcy + 0.5f * th;
        bool any = false;
        for (int i = 0; i < MAXBOX; i++) {
            const float4 pb = s_pbox[sub][i];
            const float lx = fmaxf(pb.x, tx0);
            const float ly = fmaxf(pb.y, ty0);
            const float rx = fminf(pb.z, tx1);
            const float ry = fminf(pb.w, ty1);
            if (rx > lx && ry > ly) { any = true; break; }
        }
        if (any) {
            const float dx = sp[myoff + 0] - st[myoff + 0];
            const float dy = sp[myoff + 1] - st[myoff + 1];
            const float dw = sqrtf(sp[myoff + 2]) - sqrtf(st[myoff + 2]);
            const float dh = sqrtf(sp[myoff + 3]) - sqrtf(st[myoff + 3]);
            const float dc = sp[myoff + 4] - st[myoff + 4];
            a_coord = dx * dx + dy * dy + dw * dw + dh * dh;
            a_obj   = dc * dc;
        }
    }

    // ---- deterministic reduction: warp shuffle + 16-warp smem stage ----
    #pragma unroll
    for (int o = 16; o > 0; o >>= 1) {
        a_noobj += __shfl_xor_sync(0xffffffffu, a_noobj, o);
        a_cls   += __shfl_xor_sync(0xffffffffu, a_cls,   o);
        a_coord += __shfl_xor_sync(0xffffffffu, a_coord, o);
        a_obj   += __shfl_xor_sync(0xffffffffu, a_obj,   o);
    }
    const int wid  = tid >> 5;
    const int lane = tid & 31;
    if (lane == 0) {
        s_red[0][wid] = a_noobj;
        s_red[1][wid] = a_cls;
        s_red[2][wid] = a_coord;
        s_red[3][wid] = a_obj;
    }
    __syncthreads();
    // final merge by warp 0: lane l<16 holds warp l's value, shuffle-reduce
    if (wid == 0) {
        float n  = (lane < 16) ? s_red[0][lane] : 0.0f;
        float c  = (lane < 16) ? s_red[1][lane] : 0.0f;
        float co = (lane < 16) ? s_red[2][lane] : 0.0f;
        float ob = (lane < 16) ? s_red[3][lane] : 0.0f;
        #pragma unroll
        for (int o = 8; o > 0; o >>= 1) {
            n  += __shfl_xor_sync(0xffffffffu, n,  o);
            c  += __shfl_xor_sync(0xffffffffu, c,  o);
            co += __shfl_xor_sync(0xffffffffu, co, o);
            ob += __shfl_xor_sync(0xffffffffu, ob, o);
        }
        if (lane == 0)
            g_part4[blockIdx.x] = make_float4(n, c, co, ob);
    }
}

// Stage 2: 16 blocks, each reduces 128 float4 -> one double4 (multi-SM).
__global__ void __launch_bounds__(128)
yolo_k1b()
{
    __shared__ double s_red[4][4];
    const int t = threadIdx.x;
    const float4 v = g_part4[blockIdx.x * 128 + t];
    double n = (double)v.x, c = (double)v.y, co = (double)v.z, ob = (double)v.w;

    #pragma unroll
    for (int o = 16; o > 0; o >>= 1) {
        n  += __shfl_xor_sync(0xffffffffu, n,  o);
        c  += __shfl_xor_sync(0xffffffffu, c,  o);
        co += __shfl_xor_sync(0xffffffffu, co, o);
        ob += __shfl_xor_sync(0xffffffffu, ob, o);
    }
    const int wid  = t >> 5;
    const int lane = t & 31;
    if (lane == 0) {
        s_red[0][wid] = n;
        s_red[1][wid] = c;
        s_red[2][wid] = co;
        s_red[3][wid] = ob;
    }
    __syncthreads();
    if (t == 0) {
        double4 r;
        r.x = s_red[0][0] + s_red[0][1] + s_red[0][2] + s_red[0][3];
        r.y = s_red[1][0] + s_red[1][1] + s_red[1][2] + s_red[1][3];
        r.z = s_red[2][0] + s_red[2][1] + s_red[2][2] + s_red[2][3];
        r.w = s_red[3][0] + s_red[3][1] + s_red[3][2] + s_red[3][3];
        g_mid[blockIdx.x] = r;
    }
}

// Stage 3: one warp reads 16 double4 and finishes.
__global__ void __launch_bounds__(32)
yolo_k2(float* __restrict__ out)
{
    const int t = threadIdx.x;
    double n = 0.0, c = 0.0, co = 0.0, ob = 0.0;
    if (t < NMID) {
        const double4 v = g_mid[t];
        n = v.x; c = v.y; co = v.z; ob = v.w;
    }
    #pragma unroll
    for (int o = 16; o > 0; o >>= 1) {
        n  += __shfl_xor_sync(0xffffffffu, n,  o);
        c  += __shfl_xor_sync(0xffffffffu, c,  o);
        co += __shfl_xor_sync(0xffffffffu, co, o);
        ob += __shfl_xor_sync(0xffffffffu, ob, o);
    }
    if (t == 0) {
        const double Bd      = (double)NB;
        const double cls_l   = c / Bd;
        const double obj_l   = (ob + 0.5 * n) / Bd;
        const double coord_l = co * 5.0 / Bd;
        out[0] = (float)(cls_l + obj_l + coord_l);
        out[1] = (float)cls_l;
        out[2] = (float)obj_l;
        out[3] = (float)coord_l;
    }
}

extern "C" void kernel_launch(void* const* d_in, const int* in_sizes, int n_in,
                              void* d_out, int out_size)
{
    const float* pred = (const float*)d_in[0];
    const float* targ = (const float*)d_in[1];
    float* out = (float*)d_out;

    yolo_k1 <<<NPART, 512>>>(pred, targ);
    yolo_k1b<<<NMID, 128>>>();
    yolo_k2 <<<1, 32>>>(out);
}